// round 13
// baseline (speedup 1.0000x reference)
#include <cuda_runtime.h>
#include <cuda_fp16.h>
#include <math.h>
#include <stdint.h>

#define BATCH  4096
#define OBSD   512
#define DH     1024
#define NEXP   8
#define DKK    256
#define DVV    1024
#define NTASKS 10
#define NOUT   128
#define NDH8   (NEXP * DH)          // 8192

// ------------------------- scratch (device globals) ------------------------
__device__ __half g_xh [BATCH*OBSD], g_xl [BATCH*OBSD];
__device__ __half g_h1h[BATCH*DH],   g_h1l[BATCH*DH];
__device__ __half g_hh [BATCH*DH];
__device__ __half g_e1h[(size_t)BATCH*NDH8];
__device__ __half g_e2h[(size_t)BATCH*NDH8];
__device__ __half g_vth[(size_t)BATCH*NDH8];
__device__ __half g_rh [BATCH*DVV],  g_rl [BATCH*DVV];
__device__ __half g_th [BATCH*DH],   g_tl [BATCH*DH];

__device__ __half g_Wb1h[DH*OBSD],  g_Wb1l[DH*OBSD];
__device__ __half g_Wb2h[DH*DH],    g_Wb2l[DH*DH];
__device__ __half g_We1t[NEXP*DH*DH];
__device__ __half g_We2t[NEXP*DH*DH];
__device__ __half g_Wvt [(size_t)DVV*NDH8];
__device__ __half g_Wt1h[DH*DVV],   g_Wt1l[DH*DVV];
__device__ __half g_Wlh [NOUT*DH],  g_Wll [NOUT*DH];

__device__ float g_q[DKK], g_wn[NEXP*DH], g_cn[NEXP], g_s[NEXP*BATCH];

// ------------------------- PTX helpers -------------------------------------
__device__ __forceinline__ uint32_t smem_u32(const void* p) {
    uint32_t a;
    asm("{ .reg .u64 t; cvta.to.shared.u64 t, %1; cvt.u32.u64 %0, t; }" : "=r"(a) : "l"(p));
    return a;
}
__device__ __forceinline__ void cpa16(uint32_t dst, const void* src) {
    asm volatile("cp.async.cg.shared.global [%0], [%1], 16;" :: "r"(dst), "l"(src));
}
#define CP_COMMIT() asm volatile("cp.async.commit_group;" ::: "memory")
#define CP_WAIT0()  asm volatile("cp.async.wait_group 0;" ::: "memory")
#define CP_WAIT1()  asm volatile("cp.async.wait_group 1;" ::: "memory")

#define LDSM4(r0, r1, r2, r3, addr) \
    asm volatile("ldmatrix.sync.aligned.m8n8.x4.shared.b16 {%0,%1,%2,%3}, [%4];" \
                 : "=r"(r0), "=r"(r1), "=r"(r2), "=r"(r3) : "r"(addr))

#define MMA_F16(d, a, b0v, b1v) \
    asm volatile("mma.sync.aligned.m16n8k16.row.col.f32.f16.f16.f32 " \
                 "{%0,%1,%2,%3},{%4,%5,%6,%7},{%8,%9},{%0,%1,%2,%3};" \
                 : "+f"((d)[0]), "+f"((d)[1]), "+f"((d)[2]), "+f"((d)[3]) \
                 : "r"((a)[0]), "r"((a)[1]), "r"((a)[2]), "r"((a)[3]), \
                   "r"(b0v), "r"(b1v))

enum { EPI_RELU_R = 0, EPI_RELU_S = 1, EPI_VSUM = 2, EPI_SPLIT = 3 };

// ===================== 3-pass exact GEMM (chunk 32) =========================
#define TILEB  8192                       // 128 rows * 64B
#define NSTAGE 3

template <int EPI>
__global__ __launch_bounds__(128, 2)
void mma_gemm3(const __half* __restrict__ Ah, const __half* __restrict__ Al,
               int lda,
               const __half* __restrict__ Bh, const __half* __restrict__ Bl,
               int ldb,
               const float* __restrict__ bias,
               int K,
               float* __restrict__ Cf,
               __half* __restrict__ Ch, __half* __restrict__ Cl,
               int ldc)
{
    constexpr uint32_t STG = 4 * TILEB;
    extern __shared__ char smem[];
    const uint32_t sbuf = smem_u32(smem);
    const int tid = threadIdx.x, wid = tid >> 5, lane = tid & 31;
    const int m0 = blockIdx.y * 128, n0 = blockIdx.x * 128;
    const int warp_m = (wid >> 1) * 64;
    const int warp_n = (wid & 1) * 64;

    const __half* Ab_h = Ah + (size_t)m0 * lda;
    const __half* Ab_l = Al + (size_t)m0 * lda;
    const __half* Bb_h = Bh + (size_t)n0 * ldb;
    const __half* Bb_l = Bl + (size_t)n0 * ldb;

    float acc[4][8][4];
#pragma unroll
    for (int a = 0; a < 4; a++)
#pragma unroll
        for (int b = 0; b < 8; b++)
#pragma unroll
            for (int c = 0; c < 4; c++) acc[a][b][c] = 0.f;

    const int KT = K >> 5;

    auto load_stage = [&](int kt, int s) {
        const uint32_t base = sbuf + s * STG;
        const int k0 = kt << 5;
#pragma unroll
        for (int part = 0; part < 4; part++) {
            const __half* src = (part == 0 ? Ab_h : part == 1 ? Ab_l : part == 2 ? Bb_h : Bb_l);
            const int ld = (part < 2) ? lda : ldb;
            const uint32_t dstb = base + part * TILEB;
#pragma unroll
            for (int i = 0; i < 4; i++) {
                int idx = i * 128 + tid;
                int row = idx >> 2, g = idx & 3;
                int unit = g ^ ((row >> 1) & 3);
                cpa16(dstb + (uint32_t)(row * 64 + unit * 16),
                      src + (size_t)row * ld + k0 + g * 8);
            }
        }
        CP_COMMIT();
    };

    load_stage(0, 0);
    load_stage(1, 1);

    int s = 0, ls = 2;
    for (int kt = 0; kt < KT; kt++) {
        if (kt == KT - 1) { CP_WAIT0(); } else { CP_WAIT1(); }
        __syncthreads();

        const uint32_t base = sbuf + s * STG;
#pragma unroll
        for (int kk = 0; kk < 2; kk++) {
            uint32_t bh[4][4], bl[4][4];
#pragma unroll
            for (int np = 0; np < 4; np++) {
                const uint32_t nrow = warp_n + np * 16 + ((lane >> 4) & 1) * 8 + (lane & 7);
                const uint32_t cu = (kk * 2 + ((lane >> 3) & 1)) ^ ((nrow >> 1) & 3);
                const uint32_t bd = base + 2 * TILEB + nrow * 64 + cu * 16;
                LDSM4(bh[np][0], bh[np][1], bh[np][2], bh[np][3], bd);
                LDSM4(bl[np][0], bl[np][1], bl[np][2], bl[np][3], bd + TILEB);
            }
#pragma unroll
            for (int mt = 0; mt < 4; mt++) {
                const uint32_t arow = warp_m + mt * 16 + ((lane >> 3) & 1) * 8 + (lane & 7);
                const uint32_t cu = (kk * 2 + (lane >> 4)) ^ ((arow >> 1) & 3);
                const uint32_t ad = base + arow * 64 + cu * 16;
                uint32_t ah[4], al[4];
                LDSM4(ah[0], ah[1], ah[2], ah[3], ad);
                LDSM4(al[0], al[1], al[2], al[3], ad + TILEB);
#pragma unroll
                for (int np = 0; np < 4; np++) {
                    MMA_F16(acc[mt][np * 2],     ah, bh[np][0], bh[np][1]);
                    MMA_F16(acc[mt][np * 2 + 1], ah, bh[np][2], bh[np][3]);
                }
#pragma unroll
                for (int np = 0; np < 4; np++) {
                    MMA_F16(acc[mt][np * 2],     ah, bl[np][0], bl[np][1]);
                    MMA_F16(acc[mt][np * 2 + 1], ah, bl[np][2], bl[np][3]);
                }
#pragma unroll
                for (int np = 0; np < 4; np++) {
                    MMA_F16(acc[mt][np * 2],     al, bh[np][0], bh[np][1]);
                    MMA_F16(acc[mt][np * 2 + 1], al, bh[np][2], bh[np][3]);
                }
            }
        }
        if (kt + 2 < KT) load_stage(kt + 2, ls);
        s  = (s  == NSTAGE - 1) ? 0 : s + 1;
        ls = (ls == NSTAGE - 1) ? 0 : ls + 1;
    }

    // epilogue
    const int tr = lane >> 2, tc = (lane & 3) * 2;
#pragma unroll
    for (int mt = 0; mt < 4; mt++) {
#pragma unroll
        for (int hf = 0; hf < 2; hf++) {
            const int r = m0 + warp_m + mt * 16 + tr + hf * 8;
#pragma unroll
            for (int j = 0; j < 8; j++) {
                const int col = n0 + warp_n + j * 8 + tc;
                float v0 = acc[mt][j][hf * 2]     + bias[col];
                float v1 = acc[mt][j][hf * 2 + 1] + bias[col + 1];
                if (EPI == EPI_RELU_R || EPI == EPI_RELU_S) {
                    v0 = fmaxf(v0, 0.f); v1 = fmaxf(v1, 0.f);
                    __half h0 = __float2half_rn(v0);
                    __half h1 = __float2half_rn(v1);
                    size_t o = (size_t)r * ldc + col;
                    *(__half2*)(Ch + o) = __halves2half2(h0, h1);
                    if (EPI == EPI_RELU_R) {
                        __half l0 = __float2half_rn(v0 - __half2float(h0));
                        __half l1 = __float2half_rn(v1 - __half2float(h1));
                        *(__half2*)(Cl + o) = __halves2half2(l0, l1);
                    }
                } else {   // EPI_SPLIT
                    if (col < 64) {
                        Cf[(size_t)r * 64 + col]     = v0;
                        Cf[(size_t)r * 64 + col + 1] = v1;
                    } else {
                        float l0 = fminf(fmaxf(v0, -20.f), 2.f);
                        float l1 = fminf(fmaxf(v1, -20.f), 2.f);
                        Cf[(size_t)BATCH * 64 + (size_t)r * 64 + (col - 64)]     = expf(l0);
                        Cf[(size_t)BATCH * 64 + (size_t)r * 64 + (col - 63)]     = expf(l1);
                        Cf[(size_t)2 * BATCH * 64 + (size_t)r * 64 + (col - 64)] = l0;
                        Cf[(size_t)2 * BATCH * 64 + (size_t)r * 64 + (col - 63)] = l1;
                    }
                }
            }
        }
    }
}

// ===================== 1-pass fast GEMM (chunk 64, kk-pipelined) ============
// 128-byte-row tiles; swizzle: unit' = unit ^ (row & 7).
// B fragments double-buffered across kk; A double-buffered across mt steps.
#define T1B    16384                      // 128 rows * 128B
#define STG1   (2 * T1B)                  // A, B = 32 KB
#define SMEM1  (NSTAGE * STG1)            // 98304

template <int EPI>
__global__ __launch_bounds__(128, 2)
void mma_gemm1(const __half* __restrict__ Ah, int lda, int aoffz,
               const __half* __restrict__ Bw, int ldb, int boffz,
               const float* __restrict__ bias, int biasoffz,
               int K,
               __half* __restrict__ Ch, __half* __restrict__ Cl,
               int ldc, int coffz,
               const float* __restrict__ sarr, const float* __restrict__ bvv)
{
    extern __shared__ char smem[];
    const uint32_t sbuf = smem_u32(smem);
    const int tid = threadIdx.x, wid = tid >> 5, lane = tid & 31;
    const int z = blockIdx.z;
    const int m0 = blockIdx.y * 128, n0 = blockIdx.x * 128;
    const int warp_m = (wid >> 1) * 64;
    const int warp_n = (wid & 1) * 64;

    const __half* Ab = Ah + (size_t)m0 * lda + (size_t)z * aoffz;
    const __half* Bb = Bw + (size_t)z * boffz + (size_t)n0 * ldb;

    float acc[4][8][4];
#pragma unroll
    for (int a = 0; a < 4; a++)
#pragma unroll
        for (int b = 0; b < 8; b++)
#pragma unroll
            for (int c = 0; c < 4; c++) acc[a][b][c] = 0.f;

    const int KT = K >> 6;                // chunks of 64

    auto load_stage = [&](int kt, int s) {
        const uint32_t base = sbuf + s * STG1;
        const int k0 = kt << 6;
#pragma unroll
        for (int part = 0; part < 2; part++) {
            const __half* src = (part == 0) ? Ab : Bb;
            const int ld = (part == 0) ? lda : ldb;
            const uint32_t dstb = base + part * T1B;
#pragma unroll
            for (int i = 0; i < 8; i++) {
                int idx = i * 128 + tid;
                int row = idx >> 3, g = idx & 7;
                int unit = g ^ (row & 7);
                cpa16(dstb + (uint32_t)(row * 128 + unit * 16),
                      src + (size_t)row * ld + k0 + g * 8);
            }
        }
        CP_COMMIT();
    };

    auto b_addr = [&](uint32_t base, int kk, int np) -> uint32_t {
        const uint32_t nrow = warp_n + np * 16 + ((lane >> 4) & 1) * 8 + (lane & 7);
        const uint32_t cu = (kk * 2 + ((lane >> 3) & 1)) ^ (nrow & 7);
        return base + T1B + nrow * 128 + cu * 16;
    };
    auto a_addr = [&](uint32_t base, int kk, int mt) -> uint32_t {
        const uint32_t arow = warp_m + mt * 16 + ((lane >> 3) & 1) * 8 + (lane & 7);
        const uint32_t cu = (kk * 2 + (lane >> 4)) ^ (arow & 7);
        return base + arow * 128 + cu * 16;
    };

    load_stage(0, 0);
    load_stage(1, 1);

    int s = 0, ls = 2;
    for (int kt = 0; kt < KT; kt++) {
        if (kt == KT - 1) { CP_WAIT0(); } else { CP_WAIT1(); }
        __syncthreads();

        const uint32_t base = sbuf + s * STG1;

        uint32_t bf[2][4][4], af[2][4];
        // prime: B(kk=0) all np, A(kk=0, mt=0)
#pragma unroll
        for (int np = 0; np < 4; np++)
            LDSM4(bf[0][np][0], bf[0][np][1], bf[0][np][2], bf[0][np][3],
                  b_addr(base, 0, np));
        LDSM4(af[0][0], af[0][1], af[0][2], af[0][3], a_addr(base, 0, 0));

#pragma unroll
        for (int kk = 0; kk < 4; kk++) {
            const int cb = kk & 1;
#pragma unroll
            for (int mt = 0; mt < 4; mt++) {
                const int ca = (kk * 4 + mt) & 1;
                // prefetch next A fragment (next mt, or first mt of next kk)
                if (mt < 3) {
                    LDSM4(af[ca ^ 1][0], af[ca ^ 1][1], af[ca ^ 1][2], af[ca ^ 1][3],
                          a_addr(base, kk, mt + 1));
                } else if (kk < 3) {
                    LDSM4(af[ca ^ 1][0], af[ca ^ 1][1], af[ca ^ 1][2], af[ca ^ 1][3],
                          a_addr(base, kk + 1, 0));
                }
                // prefetch one B fragment of next kk per mt step
                if (kk < 3)
                    LDSM4(bf[cb ^ 1][mt][0], bf[cb ^ 1][mt][1],
                          bf[cb ^ 1][mt][2], bf[cb ^ 1][mt][3],
                          b_addr(base, kk + 1, mt));
                // 8 MMAs for (kk, mt)
#pragma unroll
                for (int np = 0; np < 4; np++) {
                    MMA_F16(acc[mt][np * 2],     af[ca], bf[cb][np][0], bf[cb][np][1]);
                    MMA_F16(acc[mt][np * 2 + 1], af[ca], bf[cb][np][2], bf[cb][np][3]);
                }
            }
        }
        if (kt + 2 < KT) load_stage(kt + 2, ls);
        s  = (s  == NSTAGE - 1) ? 0 : s + 1;
        ls = (ls == NSTAGE - 1) ? 0 : ls + 1;
    }

    // epilogue
    const int tr = lane >> 2, tc = (lane & 3) * 2;
#pragma unroll
    for (int mt = 0; mt < 4; mt++) {
#pragma unroll
        for (int hf = 0; hf < 2; hf++) {
            const int r = m0 + warp_m + mt * 16 + tr + hf * 8;
            float sv8[NEXP];
            if (EPI == EPI_VSUM) {
#pragma unroll
                for (int n = 0; n < NEXP; n++) sv8[n] = sarr[n * BATCH + r];
            }
#pragma unroll
            for (int j = 0; j < 8; j++) {
                const int col = n0 + warp_n + j * 8 + tc;
                float v0 = acc[mt][j][hf * 2];
                float v1 = acc[mt][j][hf * 2 + 1];
                if (EPI == EPI_RELU_S) {
                    v0 += bias[(size_t)z * biasoffz + col];
                    v1 += bias[(size_t)z * biasoffz + col + 1];
                    v0 = fmaxf(v0, 0.f); v1 = fmaxf(v1, 0.f);
                    size_t o = (size_t)r * ldc + (size_t)z * coffz + col;
                    *(__half2*)(Ch + o) =
                        __halves2half2(__float2half_rn(v0), __float2half_rn(v1));
                } else {   // EPI_VSUM
#pragma unroll
                    for (int n = 0; n < NEXP; n++) {
                        v0 += bvv[n * DVV + col]     * sv8[n];
                        v1 += bvv[n * DVV + col + 1] * sv8[n];
                    }
                    __half h0 = __float2half_rn(v0);
                    __half h1 = __float2half_rn(v1);
                    __half l0 = __float2half_rn(v0 - __half2float(h0));
                    __half l1 = __float2half_rn(v1 - __half2float(h1));
                    size_t o = (size_t)r * ldc + col;
                    *(__half2*)(Ch + o) = __halves2half2(h0, h1);
                    *(__half2*)(Cl + o) = __halves2half2(l0, l1);
                }
            }
        }
    }
}

// ------------------------- prep kernels ------------------------------------
__device__ __forceinline__ void ts_body(const float* W, __half* Th, __half* Tl,
                                        int K, int N, int ors, size_t moff)
{
    __shared__ float tile[32][33];
    const int k0 = blockIdx.x * 32, n0 = blockIdx.y * 32;
    const int tx = threadIdx.x, ty = threadIdx.y;
#pragma unroll
    for (int ii = 0; ii < 2; ii++)
#pragma unroll
        for (int jj = 0; jj < 2; jj++)
            tile[ty + 16 * ii][tx + 16 * jj] =
                W[(size_t)(k0 + ty + 16 * ii) * N + n0 + tx + 16 * jj];
    __syncthreads();
#pragma unroll
    for (int ii = 0; ii < 2; ii++) {
        const int i = ty + 16 * ii;
        float v0 = tile[tx * 2][i], v1 = tile[tx * 2 + 1][i];
        __half h0 = __float2half_rn(v0), h1 = __float2half_rn(v1);
        size_t o = moff + (size_t)(n0 + i) * ors + k0 + tx * 2;
        *(__half2*)(Th + o) = __halves2half2(h0, h1);
        if (Tl) {
            __half l0 = __float2half_rn(v0 - __half2float(h0));
            __half l1 = __float2half_rn(v1 - __half2float(h1));
            *(__half2*)(Tl + o) = __halves2half2(l0, l1);
        }
    }
}

// fused base transposes: z=0 -> Wb1 (512x1024, x<16), z=1 -> Wb2 (1024x1024)
__global__ void ts_base_k(const float* __restrict__ Wb1, __half* T1h, __half* T1l,
                          const float* __restrict__ Wb2, __half* T2h, __half* T2l)
{
    if (blockIdx.z == 0) {
        if (blockIdx.x >= 16) return;
        ts_body(Wb1, T1h, T1l, OBSD, DH, OBSD, 0);
    } else {
        ts_body(Wb2, T2h, T2l, DH, DH, DH, 0);
    }
}

__global__ void transpose_split_k(const float* __restrict__ W,
                                  __half* __restrict__ Th, __half* __restrict__ Tl,
                                  int K, int N, int ors, size_t zoff)
{
    ts_body(W + (size_t)blockIdx.z * K * N, Th, Tl, K, N, ors,
            (size_t)blockIdx.z * zoff);
}

__global__ void transpose_f16_k(const float* __restrict__ W, __half* __restrict__ T,
                                int K, int N, int ors, size_t zoff)
{
    ts_body(W + (size_t)blockIdx.z * K * N, T, nullptr, K, N, ors,
            (size_t)blockIdx.z * zoff);
}

__global__ void split_k(const float* __restrict__ X, __half* __restrict__ Xh,
                        __half* __restrict__ Xl, int n)
{
    int i = (blockIdx.x * 256 + threadIdx.x) * 4;
    if (i < n) {
        float4 v = *(const float4*)(X + i);
        __half h0 = __float2half_rn(v.x), h1 = __float2half_rn(v.y);
        __half h2 = __float2half_rn(v.z), h3 = __float2half_rn(v.w);
        __half l0 = __float2half_rn(v.x - __half2float(h0));
        __half l1 = __float2half_rn(v.y - __half2float(h1));
        __half l2 = __float2half_rn(v.z - __half2float(h2));
        __half l3 = __float2half_rn(v.w - __half2float(h3));
        __half2 hp0 = __halves2half2(h0, h1), hp1 = __halves2half2(h2, h3);
        __half2 lp0 = __halves2half2(l0, l1), lp1 = __halves2half2(l2, l3);
        uint2 hu, lu;
        hu.x = *(uint32_t*)&hp0; hu.y = *(uint32_t*)&hp1;
        lu.x = *(uint32_t*)&lp0; lu.y = *(uint32_t*)&lp1;
        *(uint2*)(Xh + i) = hu;
        *(uint2*)(Xl + i) = lu;
    }
}

__global__ void prep_k(const float* __restrict__ Wq, const float* __restrict__ bq,
                       const float* __restrict__ bk, const int* __restrict__ task_id)
{
    __shared__ float qs[DKK];
    const int t = *task_id;
    const int tid = threadIdx.x;
    float qv = Wq[(size_t)(t * NTASKS + t) * DKK + tid] + bq[(size_t)t * DKK + tid];
    g_q[tid] = qv;
    qs[tid]  = qv;
    __syncthreads();
    const int w = tid >> 5, lane = tid & 31;
    float sum = 0.f;
#pragma unroll
    for (int k = lane; k < DKK; k += 32) sum += bk[(size_t)w * DKK + k] * qs[k];
#pragma unroll
    for (int o = 16; o; o >>= 1) sum += __shfl_xor_sync(0xffffffffu, sum, o);
    if (lane == 0) g_cn[w] = sum;
}

__global__ void wn_k(const float* __restrict__ Wk)
{
    const int tid = threadIdx.x, w = tid >> 5, lane = tid & 31;
    const int row = blockIdx.x * 8 + w;
    const float* wr = Wk + (size_t)row * DKK;
    float sum = 0.f;
#pragma unroll
    for (int k = lane; k < DKK; k += 32) sum += wr[k] * g_q[k];
#pragma unroll
    for (int o = 16; o; o >>= 1) sum += __shfl_xor_sync(0xffffffffu, sum, o);
    if (lane == 0) g_wn[row] = sum;
}

__global__ void expkq_scale_k()
{
    __shared__ uint32_t shh[8][512];
    const int tid = threadIdx.x, w = tid >> 5, lane = tid & 31;
    const int row = blockIdx.x * 8 + w;
    const int n = blockIdx.y;
    const size_t base = (size_t)row * NDH8 + (size_t)n * DH;
    const float* wn = g_wn + n * DH;
    float sum = 0.f;
#pragma unroll 4
    for (int it = 0; it < 16; it++) {
        const int k2 = it * 32 + lane;
        uint32_t h2 = *(const uint32_t*)(g_e2h + base + k2 * 2);
        shh[w][k2] = h2;
        float2 hb = __half22float2(*(__half2*)&h2);
        float2 wv = *(const float2*)(wn + k2 * 2);
        sum += hb.x * wv.x + hb.y * wv.y;
    }
#pragma unroll
    for (int o = 16; o; o >>= 1) sum += __shfl_xor_sync(0xffffffffu, sum, o);
    const float s = sum + g_cn[n];
    if (lane == 0) g_s[n * BATCH + row] = s;
#pragma unroll 4
    for (int it = 0; it < 16; it++) {
        const int k2 = it * 32 + lane;
        uint32_t h2 = shh[w][k2];
        float2 hb = __half22float2(*(__half2*)&h2);
        *(__half2*)(g_vth + base + k2 * 2) =
            __halves2half2(__float2half_rn(hb.x * s), __float2half_rn(hb.y * s));
    }
}

// ------------------------- launch ------------------------------------------
extern "C" void kernel_launch(void* const* d_in, const int* in_sizes, int n_in,
                              void* d_out, int out_size)
{
    const float* x    = (const float*)d_in[0];
    const int*   task = (const int*)  d_in[1];
    const float* Wb1  = (const float*)d_in[2];
    const float* bb1  = (const float*)d_in[3];
    const float* Wb2  = (const float*)d_in[4];
    const float* bb2  = (const float*)d_in[5];
    const float* We1  = (const float*)d_in[6];
    const float* be1  = (const float*)d_in[7];
    const float* We2  = (const float*)d_in[8];
    const float* be2  = (const float*)d_in[9];
    const float* Wv   = (const float*)d_in[10];
    const float* bv   = (const float*)d_in[11];
    const float* Wk   = (const float*)d_in[12];
    const float* bk   = (const float*)d_in[13];
    const float* Wq   = (const float*)d_in[14];
    const float* bq   = (const float*)d_in[15];
    const float* Wt1  = (const float*)d_in[16];
    const float* bt1  = (const float*)d_in[17];
    const float* Wl   = (const float*)d_in[18];
    const float* bl   = (const float*)d_in[19];
    float* out = (float*)d_out;

#define SYM(p, s) do { void* _t; cudaGetSymbolAddress(&_t, s); p = (decltype(p))_t; } while (0)
    __half *xh, *xl, *h1h, *h1l, *hh, *e1h, *e2h, *vth, *rh, *rl, *th, *tl;
    __half *Wb1h, *Wb1l, *Wb2h, *Wb2l, *We1t, *We2t, *Wvt, *Wt1h, *Wt1l, *Wlh, *Wll;
    float *sc;
    SYM(xh, g_xh);  SYM(xl, g_xl);  SYM(h1h, g_h1h); SYM(h1l, g_h1l);
    SYM(hh, g_hh);  SYM(e1h, g_e1h); SYM(e2h, g_e2h); SYM(vth, g_vth);
    SYM(rh, g_rh);  SYM(rl, g_rl);  SYM(th, g_th);  SYM(tl, g_tl);
    SYM(Wb1h, g_Wb1h); SYM(Wb1l, g_Wb1l); SYM(Wb2h, g_Wb2h); SYM(Wb2l, g_Wb2l);
    SYM(We1t, g_We1t); SYM(We2t, g_We2t); SYM(Wvt, g_Wvt);
    SYM(Wt1h, g_Wt1h); SYM(Wt1l, g_Wt1l); SYM(Wlh, g_Wlh); SYM(Wll, g_Wll);
    SYM(sc, g_s);

    const int SMEM_P3 = NSTAGE * 4 * TILEB;   // 98304
    cudaFuncSetAttribute(mma_gemm3<EPI_RELU_R>, cudaFuncAttributeMaxDynamicSharedMemorySize, SMEM_P3);
    cudaFuncSetAttribute(mma_gemm3<EPI_RELU_S>, cudaFuncAttributeMaxDynamicSharedMemorySize, SMEM_P3);
    cudaFuncSetAttribute(mma_gemm3<EPI_SPLIT >, cudaFuncAttributeMaxDynamicSharedMemorySize, SMEM_P3);
    cudaFuncSetAttribute(mma_gemm1<EPI_RELU_S>, cudaFuncAttributeMaxDynamicSharedMemorySize, SMEM1);
    cudaFuncSetAttribute(mma_gemm1<EPI_VSUM  >, cudaFuncAttributeMaxDynamicSharedMemorySize, SMEM1);

    dim3 tb(16, 16);

    split_k<<<(BATCH * OBSD / 4 + 255) / 256, 256>>>(x, xh, xl, BATCH * OBSD);            // 0
    ts_base_k<<<dim3(32, 32, 2), tb>>>(Wb1, Wb1h, Wb1l, Wb2, Wb2h, Wb2l);                 // 1
    transpose_f16_k<<<dim3(DH / 32, DH / 32, NEXP), tb>>>(We1, We1t, DH, DH, DH, (size_t)DH * DH); // 2

    // base1 (exact 3-pass) -> h1 rails
    mma_gemm3<EPI_RELU_R><<<dim3(8, 32), 128, SMEM_P3>>>(                                 // 3
        xh, xl, OBSD, Wb1h, Wb1l, OBSD, bb1, OBSD, nullptr, h1h, h1l, DH);
    // base2 (exact 3-pass) -> hh single rail
    mma_gemm3<EPI_RELU_S><<<dim3(8, 32), 128, SMEM_P3>>>(                                 // 4
        h1h, h1l, DH, Wb2h, Wb2l, DH, bb2, DH, nullptr, hh, nullptr, DH);

    // e1: one GEMM, N = 8192, 1-pass kk-pipelined  (profiled at idx 5)
    mma_gemm1<EPI_RELU_S><<<dim3(NDH8 / 128, 32), 128, SMEM1>>>(                          // 5
        hh, DH, 0, We1t, DH, 0, be1, 0, DH, e1h, nullptr, NDH8, 0, nullptr, nullptr);

    transpose_f16_k<<<dim3(DH / 32, DH / 32, NEXP), tb>>>(We2, We2t, DH, DH, DH, (size_t)DH * DH); // 6

    // e2: z-batched block-diagonal, 1-pass
    mma_gemm1<EPI_RELU_S><<<dim3(DH / 128, 32, NEXP), 128, SMEM1>>>(                      // 7
        e1h, NDH8, DH, We2t, DH, DH * DH, be2, DH, DH, e2h, nullptr, NDH8, DH,
        nullptr, nullptr);

    prep_k<<<1, 256>>>(Wq, bq, bk, task);                                                 // 8
    wn_k<<<NEXP * DH / 8, 256>>>(Wk);                                                     // 9
    expkq_scale_k<<<dim3(BATCH / 8, NEXP), 256>>>();                                      // 10

    transpose_f16_k<<<dim3(DH / 32, DVV / 32, NEXP), tb>>>(Wv, Wvt, DH, DVV, NDH8, (size_t)DH); // 11

    // fused v-sum: K = 8192, 1-pass -> res rails
    mma_gemm1<EPI_VSUM><<<dim3(DVV / 128, 32), 128, SMEM1>>>(                             // 12
        vth, NDH8, 0, Wvt, NDH8, 0, nullptr, 0, NDH8, rh, rl, DVV, 0, sc, bv);

    transpose_split_k<<<dim3(DVV / 32, DH / 32, 1), tb>>>(Wt1, Wt1h, Wt1l, DVV, DH, DVV, 0); // 13
    // tower (exact 3-pass) -> th rails
    mma_gemm3<EPI_RELU_R><<<dim3(DH / 128, 32), 128, SMEM_P3>>>(                          // 14
        rh, rl, DVV, Wt1h, Wt1l, DVV, bt1, DVV, nullptr, th, tl, DH);

    transpose_split_k<<<dim3(DH / 32, NOUT / 32, 1), tb>>>(Wl, Wlh, Wll, DH, NOUT, DH, 0);   // 15
    // head (exact 3-pass)
    mma_gemm3<EPI_SPLIT><<<dim3(1, 32), 128, SMEM_P3>>>(                                  // 16
        th, tl, DH, Wlh, Wll, DH, bl, DH, out, nullptr, nullptr, NOUT);
}

// round 14
// speedup vs baseline: 1.0169x; 1.0169x over previous
#include <cuda_runtime.h>
#include <cuda_fp16.h>
#include <math.h>
#include <stdint.h>

#define BATCH  4096
#define OBSD   512
#define DH     1024
#define NEXP   8
#define DKK    256
#define DVV    1024
#define NTASKS 10
#define NOUT   128
#define NDH8   (NEXP * DH)          // 8192

// ------------------------- scratch (device globals) ------------------------
__device__ __half g_xh [BATCH*OBSD], g_xl [BATCH*OBSD];
__device__ __half g_h1h[BATCH*DH],   g_h1l[BATCH*DH];
__device__ __half g_hh [BATCH*DH];
__device__ __half g_e1h[(size_t)BATCH*NDH8];
__device__ __half g_e2h[(size_t)BATCH*NDH8];
__device__ __half g_vth[(size_t)BATCH*NDH8];
__device__ __half g_rh [BATCH*DVV],  g_rl [BATCH*DVV];
__device__ __half g_th [BATCH*DH],   g_tl [BATCH*DH];

__device__ __half g_Wb1h[DH*OBSD],  g_Wb1l[DH*OBSD];
__device__ __half g_Wb2h[DH*DH],    g_Wb2l[DH*DH];
__device__ __half g_We1t[NEXP*DH*DH];
__device__ __half g_We2t[NEXP*DH*DH];
__device__ __half g_Wvt [(size_t)DVV*NDH8];
__device__ __half g_Wt1h[DH*DVV],   g_Wt1l[DH*DVV];
__device__ __half g_Wlh [NOUT*DH],  g_Wll [NOUT*DH];

__device__ float g_q[DKK], g_wn[NEXP*DH], g_cn[NEXP], g_s[NEXP*BATCH];

// ------------------------- PTX helpers -------------------------------------
__device__ __forceinline__ uint32_t smem_u32(const void* p) {
    uint32_t a;
    asm("{ .reg .u64 t; cvta.to.shared.u64 t, %1; cvt.u32.u64 %0, t; }" : "=r"(a) : "l"(p));
    return a;
}
__device__ __forceinline__ void cpa16(uint32_t dst, const void* src) {
    asm volatile("cp.async.cg.shared.global [%0], [%1], 16;" :: "r"(dst), "l"(src));
}
#define CP_COMMIT() asm volatile("cp.async.commit_group;" ::: "memory")
#define CP_WAIT0()  asm volatile("cp.async.wait_group 0;" ::: "memory")
#define CP_WAIT1()  asm volatile("cp.async.wait_group 1;" ::: "memory")

#define LDSM4(r0, r1, r2, r3, addr) \
    asm volatile("ldmatrix.sync.aligned.m8n8.x4.shared.b16 {%0,%1,%2,%3}, [%4];" \
                 : "=r"(r0), "=r"(r1), "=r"(r2), "=r"(r3) : "r"(addr))

#define MMA_F16(d, a, b0v, b1v) \
    asm volatile("mma.sync.aligned.m16n8k16.row.col.f32.f16.f16.f32 " \
                 "{%0,%1,%2,%3},{%4,%5,%6,%7},{%8,%9},{%0,%1,%2,%3};" \
                 : "+f"((d)[0]), "+f"((d)[1]), "+f"((d)[2]), "+f"((d)[3]) \
                 : "r"((a)[0]), "r"((a)[1]), "r"((a)[2]), "r"((a)[3]), \
                   "r"(b0v), "r"(b1v))

enum { EPI_RELU_R = 0, EPI_RELU_S = 1, EPI_VSUM = 2, EPI_SPLIT = 3 };

// ===================== 3-pass exact GEMM (chunk 32) =========================
#define TILEB  8192                       // 128 rows * 64B
#define NSTAGE 3

template <int EPI>
__global__ __launch_bounds__(128, 2)
void mma_gemm3(const __half* __restrict__ Ah, const __half* __restrict__ Al,
               int lda,
               const __half* __restrict__ Bh, const __half* __restrict__ Bl,
               int ldb,
               const float* __restrict__ bias,
               int K,
               float* __restrict__ Cf,
               __half* __restrict__ Ch, __half* __restrict__ Cl,
               int ldc)
{
    constexpr uint32_t STG = 4 * TILEB;
    extern __shared__ char smem[];
    const uint32_t sbuf = smem_u32(smem);
    const int tid = threadIdx.x, wid = tid >> 5, lane = tid & 31;
    const int m0 = blockIdx.y * 128, n0 = blockIdx.x * 128;
    const int warp_m = (wid >> 1) * 64;
    const int warp_n = (wid & 1) * 64;

    const __half* Ab_h = Ah + (size_t)m0 * lda;
    const __half* Ab_l = Al + (size_t)m0 * lda;
    const __half* Bb_h = Bh + (size_t)n0 * ldb;
    const __half* Bb_l = Bl + (size_t)n0 * ldb;

    float acc[4][8][4];
#pragma unroll
    for (int a = 0; a < 4; a++)
#pragma unroll
        for (int b = 0; b < 8; b++)
#pragma unroll
            for (int c = 0; c < 4; c++) acc[a][b][c] = 0.f;

    const int KT = K >> 5;

    auto load_stage = [&](int kt, int s) {
        const uint32_t base = sbuf + s * STG;
        const int k0 = kt << 5;
#pragma unroll
        for (int part = 0; part < 4; part++) {
            const __half* src = (part == 0 ? Ab_h : part == 1 ? Ab_l : part == 2 ? Bb_h : Bb_l);
            const int ld = (part < 2) ? lda : ldb;
            const uint32_t dstb = base + part * TILEB;
#pragma unroll
            for (int i = 0; i < 4; i++) {
                int idx = i * 128 + tid;
                int row = idx >> 2, g = idx & 3;
                int unit = g ^ ((row >> 1) & 3);
                cpa16(dstb + (uint32_t)(row * 64 + unit * 16),
                      src + (size_t)row * ld + k0 + g * 8);
            }
        }
        CP_COMMIT();
    };

    load_stage(0, 0);
    load_stage(1, 1);

    int s = 0, ls = 2;
    for (int kt = 0; kt < KT; kt++) {
        if (kt == KT - 1) { CP_WAIT0(); } else { CP_WAIT1(); }
        __syncthreads();

        const uint32_t base = sbuf + s * STG;
#pragma unroll
        for (int kk = 0; kk < 2; kk++) {
            uint32_t bh[4][4], bl[4][4];
#pragma unroll
            for (int np = 0; np < 4; np++) {
                const uint32_t nrow = warp_n + np * 16 + ((lane >> 4) & 1) * 8 + (lane & 7);
                const uint32_t cu = (kk * 2 + ((lane >> 3) & 1)) ^ ((nrow >> 1) & 3);
                const uint32_t bd = base + 2 * TILEB + nrow * 64 + cu * 16;
                LDSM4(bh[np][0], bh[np][1], bh[np][2], bh[np][3], bd);
                LDSM4(bl[np][0], bl[np][1], bl[np][2], bl[np][3], bd + TILEB);
            }
#pragma unroll
            for (int mt = 0; mt < 4; mt++) {
                const uint32_t arow = warp_m + mt * 16 + ((lane >> 3) & 1) * 8 + (lane & 7);
                const uint32_t cu = (kk * 2 + (lane >> 4)) ^ ((arow >> 1) & 3);
                const uint32_t ad = base + arow * 64 + cu * 16;
                uint32_t ah[4], al[4];
                LDSM4(ah[0], ah[1], ah[2], ah[3], ad);
                LDSM4(al[0], al[1], al[2], al[3], ad + TILEB);
#pragma unroll
                for (int np = 0; np < 4; np++) {
                    MMA_F16(acc[mt][np * 2],     ah, bh[np][0], bh[np][1]);
                    MMA_F16(acc[mt][np * 2 + 1], ah, bh[np][2], bh[np][3]);
                }
#pragma unroll
                for (int np = 0; np < 4; np++) {
                    MMA_F16(acc[mt][np * 2],     ah, bl[np][0], bl[np][1]);
                    MMA_F16(acc[mt][np * 2 + 1], ah, bl[np][2], bl[np][3]);
                }
#pragma unroll
                for (int np = 0; np < 4; np++) {
                    MMA_F16(acc[mt][np * 2],     al, bh[np][0], bh[np][1]);
                    MMA_F16(acc[mt][np * 2 + 1], al, bh[np][2], bh[np][3]);
                }
            }
        }
        if (kt + 2 < KT) load_stage(kt + 2, ls);
        s  = (s  == NSTAGE - 1) ? 0 : s + 1;
        ls = (ls == NSTAGE - 1) ? 0 : ls + 1;
    }

    const int tr = lane >> 2, tc = (lane & 3) * 2;
#pragma unroll
    for (int mt = 0; mt < 4; mt++) {
#pragma unroll
        for (int hf = 0; hf < 2; hf++) {
            const int r = m0 + warp_m + mt * 16 + tr + hf * 8;
#pragma unroll
            for (int j = 0; j < 8; j++) {
                const int col = n0 + warp_n + j * 8 + tc;
                float v0 = acc[mt][j][hf * 2]     + bias[col];
                float v1 = acc[mt][j][hf * 2 + 1] + bias[col + 1];
                if (EPI == EPI_RELU_R || EPI == EPI_RELU_S) {
                    v0 = fmaxf(v0, 0.f); v1 = fmaxf(v1, 0.f);
                    __half h0 = __float2half_rn(v0);
                    __half h1 = __float2half_rn(v1);
                    size_t o = (size_t)r * ldc + col;
                    *(__half2*)(Ch + o) = __halves2half2(h0, h1);
                    if (EPI == EPI_RELU_R) {
                        __half l0 = __float2half_rn(v0 - __half2float(h0));
                        __half l1 = __float2half_rn(v1 - __half2float(h1));
                        *(__half2*)(Cl + o) = __halves2half2(l0, l1);
                    }
                } else {   // EPI_SPLIT
                    if (col < 64) {
                        Cf[(size_t)r * 64 + col]     = v0;
                        Cf[(size_t)r * 64 + col + 1] = v1;
                    } else {
                        float l0 = fminf(fmaxf(v0, -20.f), 2.f);
                        float l1 = fminf(fmaxf(v1, -20.f), 2.f);
                        Cf[(size_t)BATCH * 64 + (size_t)r * 64 + (col - 64)]     = expf(l0);
                        Cf[(size_t)BATCH * 64 + (size_t)r * 64 + (col - 63)]     = expf(l1);
                        Cf[(size_t)2 * BATCH * 64 + (size_t)r * 64 + (col - 64)] = l0;
                        Cf[(size_t)2 * BATCH * 64 + (size_t)r * 64 + (col - 63)] = l1;
                    }
                }
            }
        }
    }
}

// ===================== 1-pass fast GEMM (chunk 64) ==========================
#define T1B    16384                      // 128 rows * 128B
#define STG1   (2 * T1B)                  // A, B = 32 KB
#define SMEM1  (NSTAGE * STG1)            // 98304

template <int EPI>
__global__ __launch_bounds__(128, 2)
void mma_gemm1(const __half* __restrict__ Ah, int lda, int aoffz,
               const __half* __restrict__ Bw, int ldb, int boffz,
               const float* __restrict__ bias, int biasoffz,
               int K,
               __half* __restrict__ Ch, __half* __restrict__ Cl,
               int ldc, int coffz,
               const float* __restrict__ sarr, const float* __restrict__ bvv)
{
    extern __shared__ char smem[];
    const uint32_t sbuf = smem_u32(smem);
    const int tid = threadIdx.x, wid = tid >> 5, lane = tid & 31;
    const int z = blockIdx.z;
    const int m0 = blockIdx.y * 128, n0 = blockIdx.x * 128;
    const int warp_m = (wid >> 1) * 64;
    const int warp_n = (wid & 1) * 64;

    const __half* Ab = Ah + (size_t)m0 * lda + (size_t)z * aoffz;
    const __half* Bb = Bw + (size_t)z * boffz + (size_t)n0 * ldb;

    float acc[4][8][4];
#pragma unroll
    for (int a = 0; a < 4; a++)
#pragma unroll
        for (int b = 0; b < 8; b++)
#pragma unroll
            for (int c = 0; c < 4; c++) acc[a][b][c] = 0.f;

    const int KT = K >> 6;

    auto load_stage = [&](int kt, int s) {
        const uint32_t base = sbuf + s * STG1;
        const int k0 = kt << 6;
#pragma unroll
        for (int part = 0; part < 2; part++) {
            const __half* src = (part == 0) ? Ab : Bb;
            const int ld = (part == 0) ? lda : ldb;
            const uint32_t dstb = base + part * T1B;
#pragma unroll
            for (int i = 0; i < 8; i++) {
                int idx = i * 128 + tid;
                int row = idx >> 3, g = idx & 7;
                int unit = g ^ (row & 7);
                cpa16(dstb + (uint32_t)(row * 128 + unit * 16),
                      src + (size_t)row * ld + k0 + g * 8);
            }
        }
        CP_COMMIT();
    };

    load_stage(0, 0);
    load_stage(1, 1);

    int s = 0, ls = 2;
    for (int kt = 0; kt < KT; kt++) {
        if (kt == KT - 1) { CP_WAIT0(); } else { CP_WAIT1(); }
        __syncthreads();

        const uint32_t base = sbuf + s * STG1;
#pragma unroll
        for (int kk = 0; kk < 4; kk++) {
            uint32_t bh[4][4];
#pragma unroll
            for (int np = 0; np < 4; np++) {
                const uint32_t nrow = warp_n + np * 16 + ((lane >> 4) & 1) * 8 + (lane & 7);
                const uint32_t cu = (kk * 2 + ((lane >> 3) & 1)) ^ (nrow & 7);
                const uint32_t bd = base + T1B + nrow * 128 + cu * 16;
                LDSM4(bh[np][0], bh[np][1], bh[np][2], bh[np][3], bd);
            }
#pragma unroll
            for (int mt = 0; mt < 4; mt++) {
                const uint32_t arow = warp_m + mt * 16 + ((lane >> 3) & 1) * 8 + (lane & 7);
                const uint32_t cu = (kk * 2 + (lane >> 4)) ^ (arow & 7);
                const uint32_t ad = base + arow * 128 + cu * 16;
                uint32_t ah[4];
                LDSM4(ah[0], ah[1], ah[2], ah[3], ad);
#pragma unroll
                for (int np = 0; np < 4; np++) {
                    MMA_F16(acc[mt][np * 2],     ah, bh[np][0], bh[np][1]);
                    MMA_F16(acc[mt][np * 2 + 1], ah, bh[np][2], bh[np][3]);
                }
            }
        }
        if (kt + 2 < KT) load_stage(kt + 2, ls);
        s  = (s  == NSTAGE - 1) ? 0 : s + 1;
        ls = (ls == NSTAGE - 1) ? 0 : ls + 1;
    }

    const int tr = lane >> 2, tc = (lane & 3) * 2;
#pragma unroll
    for (int mt = 0; mt < 4; mt++) {
#pragma unroll
        for (int hf = 0; hf < 2; hf++) {
            const int r = m0 + warp_m + mt * 16 + tr + hf * 8;
            float sv8[NEXP];
            if (EPI == EPI_VSUM) {
#pragma unroll
                for (int n = 0; n < NEXP; n++) sv8[n] = sarr[n * BATCH + r];
            }
#pragma unroll
            for (int j = 0; j < 8; j++) {
                const int col = n0 + warp_n + j * 8 + tc;
                float v0 = acc[mt][j][hf * 2];
                float v1 = acc[mt][j][hf * 2 + 1];
                if (EPI == EPI_RELU_S) {
                    v0 += bias[(size_t)z * biasoffz + col];
                    v1 += bias[(size_t)z * biasoffz + col + 1];
                    v0 = fmaxf(v0, 0.f); v1 = fmaxf(v1, 0.f);
                    size_t o = (size_t)r * ldc + (size_t)z * coffz + col;
                    *(__half2*)(Ch + o) =
                        __halves2half2(__float2half_rn(v0), __float2half_rn(v1));
                } else {   // EPI_VSUM
#pragma unroll
                    for (int n = 0; n < NEXP; n++) {
                        v0 += bvv[n * DVV + col]     * sv8[n];
                        v1 += bvv[n * DVV + col + 1] * sv8[n];
                    }
                    __half h0 = __float2half_rn(v0);
                    __half h1 = __float2half_rn(v1);
                    __half l0 = __float2half_rn(v0 - __half2float(h0));
                    __half l1 = __float2half_rn(v1 - __half2float(h1));
                    size_t o = (size_t)r * ldc + col;
                    *(__half2*)(Ch + o) = __halves2half2(h0, h1);
                    *(__half2*)(Cl + o) = __halves2half2(l0, l1);
                }
            }
        }
    }
}

// ------------------------- prep kernels ------------------------------------
__device__ __forceinline__ void ts_body(const float* W, __half* Th, __half* Tl,
                                        int K, int N, int ors, size_t moff)
{
    __shared__ float tile[32][33];
    const int k0 = blockIdx.x * 32, n0 = blockIdx.y * 32;
    const int tx = threadIdx.x, ty = threadIdx.y;
#pragma unroll
    for (int ii = 0; ii < 2; ii++)
#pragma unroll
        for (int jj = 0; jj < 2; jj++)
            tile[ty + 16 * ii][tx + 16 * jj] =
                W[(size_t)(k0 + ty + 16 * ii) * N + n0 + tx + 16 * jj];
    __syncthreads();
#pragma unroll
    for (int ii = 0; ii < 2; ii++) {
        const int i = ty + 16 * ii;
        float v0 = tile[tx * 2][i], v1 = tile[tx * 2 + 1][i];
        __half h0 = __float2half_rn(v0), h1 = __float2half_rn(v1);
        size_t o = moff + (size_t)(n0 + i) * ors + k0 + tx * 2;
        *(__half2*)(Th + o) = __halves2half2(h0, h1);
        if (Tl) {
            __half l0 = __float2half_rn(v0 - __half2float(h0));
            __half l1 = __float2half_rn(v1 - __half2float(h1));
            *(__half2*)(Tl + o) = __halves2half2(l0, l1);
        }
    }
}

__global__ void ts_base_k(const float* __restrict__ Wb1, __half* T1h, __half* T1l,
                          const float* __restrict__ Wb2, __half* T2h, __half* T2l)
{
    if (blockIdx.z == 0) {
        if (blockIdx.x >= 16) return;
        ts_body(Wb1, T1h, T1l, OBSD, DH, OBSD, 0);
    } else {
        ts_body(Wb2, T2h, T2l, DH, DH, DH, 0);
    }
}

__global__ void transpose_split_k(const float* __restrict__ W,
                                  __half* __restrict__ Th, __half* __restrict__ Tl,
                                  int K, int N, int ors, size_t zoff)
{
    ts_body(W + (size_t)blockIdx.z * K * N, Th, Tl, K, N, ors,
            (size_t)blockIdx.z * zoff);
}

__global__ void transpose_f16_k(const float* __restrict__ W, __half* __restrict__ T,
                                int K, int N, int ors, size_t zoff)
{
    ts_body(W + (size_t)blockIdx.z * K * N, T, nullptr, K, N, ors,
            (size_t)blockIdx.z * zoff);
}

__global__ void split_k(const float* __restrict__ X, __half* __restrict__ Xh,
                        __half* __restrict__ Xl, int n)
{
    int i = (blockIdx.x * 256 + threadIdx.x) * 4;
    if (i < n) {
        float4 v = *(const float4*)(X + i);
        __half h0 = __float2half_rn(v.x), h1 = __float2half_rn(v.y);
        __half h2 = __float2half_rn(v.z), h3 = __float2half_rn(v.w);
        __half l0 = __float2half_rn(v.x - __half2float(h0));
        __half l1 = __float2half_rn(v.y - __half2float(h1));
        __half l2 = __float2half_rn(v.z - __half2float(h2));
        __half l3 = __float2half_rn(v.w - __half2float(h3));
        __half2 hp0 = __halves2half2(h0, h1), hp1 = __halves2half2(h2, h3);
        __half2 lp0 = __halves2half2(l0, l1), lp1 = __halves2half2(l2, l3);
        uint2 hu, lu;
        hu.x = *(uint32_t*)&hp0; hu.y = *(uint32_t*)&hp1;
        lu.x = *(uint32_t*)&lp0; lu.y = *(uint32_t*)&lp1;
        *(uint2*)(Xh + i) = hu;
        *(uint2*)(Xl + i) = lu;
    }
}

__global__ void prep_k(const float* __restrict__ Wq, const float* __restrict__ bq,
                       const float* __restrict__ bk, const int* __restrict__ task_id)
{
    __shared__ float qs[DKK];
    const int t = *task_id;
    const int tid = threadIdx.x;
    float qv = Wq[(size_t)(t * NTASKS + t) * DKK + tid] + bq[(size_t)t * DKK + tid];
    g_q[tid] = qv;
    qs[tid]  = qv;
    __syncthreads();
    const int w = tid >> 5, lane = tid & 31;
    float sum = 0.f;
#pragma unroll
    for (int k = lane; k < DKK; k += 32) sum += bk[(size_t)w * DKK + k] * qs[k];
#pragma unroll
    for (int o = 16; o; o >>= 1) sum += __shfl_xor_sync(0xffffffffu, sum, o);
    if (lane == 0) g_cn[w] = sum;
}

__global__ void wn_k(const float* __restrict__ Wk)
{
    const int tid = threadIdx.x, w = tid >> 5, lane = tid & 31;
    const int row = blockIdx.x * 8 + w;
    const float* wr = Wk + (size_t)row * DKK;
    float sum = 0.f;
#pragma unroll
    for (int k = lane; k < DKK; k += 32) sum += wr[k] * g_q[k];
#pragma unroll
    for (int o = 16; o; o >>= 1) sum += __shfl_xor_sync(0xffffffffu, sum, o);
    if (lane == 0) g_wn[row] = sum;
}

__global__ void expkq_scale_k()
{
    __shared__ uint32_t shh[8][512];
    const int tid = threadIdx.x, w = tid >> 5, lane = tid & 31;
    const int row = blockIdx.x * 8 + w;
    const int n = blockIdx.y;
    const size_t base = (size_t)row * NDH8 + (size_t)n * DH;
    const float* wn = g_wn + n * DH;
    float sum = 0.f;
#pragma unroll 4
    for (int it = 0; it < 16; it++) {
        const int k2 = it * 32 + lane;
        uint32_t h2 = *(const uint32_t*)(g_e2h + base + k2 * 2);
        shh[w][k2] = h2;
        float2 hb = __half22float2(*(__half2*)&h2);
        float2 wv = *(const float2*)(wn + k2 * 2);
        sum += hb.x * wv.x + hb.y * wv.y;
    }
#pragma unroll
    for (int o = 16; o; o >>= 1) sum += __shfl_xor_sync(0xffffffffu, sum, o);
    const float s = sum + g_cn[n];
    if (lane == 0) g_s[n * BATCH + row] = s;
#pragma unroll 4
    for (int it = 0; it < 16; it++) {
        const int k2 = it * 32 + lane;
        uint32_t h2 = shh[w][k2];
        float2 hb = __half22float2(*(__half2*)&h2);
        *(__half2*)(g_vth + base + k2 * 2) =
            __halves2half2(__float2half_rn(hb.x * s), __float2half_rn(hb.y * s));
    }
}

// ------------------------- launch ------------------------------------------
extern "C" void kernel_launch(void* const* d_in, const int* in_sizes, int n_in,
                              void* d_out, int out_size)
{
    const float* x    = (const float*)d_in[0];
    const int*   task = (const int*)  d_in[1];
    const float* Wb1  = (const float*)d_in[2];
    const float* bb1  = (const float*)d_in[3];
    const float* Wb2  = (const float*)d_in[4];
    const float* bb2  = (const float*)d_in[5];
    const float* We1  = (const float*)d_in[6];
    const float* be1  = (const float*)d_in[7];
    const float* We2  = (const float*)d_in[8];
    const float* be2  = (const float*)d_in[9];
    const float* Wv   = (const float*)d_in[10];
    const float* bv   = (const float*)d_in[11];
    const float* Wk   = (const float*)d_in[12];
    const float* bk   = (const float*)d_in[13];
    const float* Wq   = (const float*)d_in[14];
    const float* bq   = (const float*)d_in[15];
    const float* Wt1  = (const float*)d_in[16];
    const float* bt1  = (const float*)d_in[17];
    const float* Wl   = (const float*)d_in[18];
    const float* bl   = (const float*)d_in[19];
    float* out = (float*)d_out;

#define SYM(p, s) do { void* _t; cudaGetSymbolAddress(&_t, s); p = (decltype(p))_t; } while (0)
    __half *xh, *xl, *h1h, *h1l, *hh, *e1h, *e2h, *vth, *rh, *rl, *th, *tl;
    __half *Wb1h, *Wb1l, *Wb2h, *Wb2l, *We1t, *We2t, *Wvt, *Wt1h, *Wt1l, *Wlh, *Wll;
    float *sc;
    SYM(xh, g_xh);  SYM(xl, g_xl);  SYM(h1h, g_h1h); SYM(h1l, g_h1l);
    SYM(hh, g_hh);  SYM(e1h, g_e1h); SYM(e2h, g_e2h); SYM(vth, g_vth);
    SYM(rh, g_rh);  SYM(rl, g_rl);  SYM(th, g_th);  SYM(tl, g_tl);
    SYM(Wb1h, g_Wb1h); SYM(Wb1l, g_Wb1l); SYM(Wb2h, g_Wb2h); SYM(Wb2l, g_Wb2l);
    SYM(We1t, g_We1t); SYM(We2t, g_We2t); SYM(Wvt, g_Wvt);
    SYM(Wt1h, g_Wt1h); SYM(Wt1l, g_Wt1l); SYM(Wlh, g_Wlh); SYM(Wll, g_Wll);
    SYM(sc, g_s);

    const int SMEM_P3 = NSTAGE * 4 * TILEB;   // 98304
    cudaFuncSetAttribute(mma_gemm3<EPI_RELU_R>, cudaFuncAttributeMaxDynamicSharedMemorySize, SMEM_P3);
    cudaFuncSetAttribute(mma_gemm3<EPI_RELU_S>, cudaFuncAttributeMaxDynamicSharedMemorySize, SMEM_P3);
    cudaFuncSetAttribute(mma_gemm3<EPI_SPLIT >, cudaFuncAttributeMaxDynamicSharedMemorySize, SMEM_P3);
    cudaFuncSetAttribute(mma_gemm1<EPI_RELU_S>, cudaFuncAttributeMaxDynamicSharedMemorySize, SMEM1);
    cudaFuncSetAttribute(mma_gemm1<EPI_VSUM  >, cudaFuncAttributeMaxDynamicSharedMemorySize, SMEM1);

    // side stream + events: created ONCE on the first (uncaptured) call,
    // reused inside graph capture via event fork/join.
    static cudaStream_t sW = nullptr;
    static cudaEvent_t evIn = nullptr, evWe1, evWe2, evWv, evWt1, evWl, evWn;
    if (!sW) {
        cudaStreamCreateWithFlags(&sW, cudaStreamNonBlocking);
        cudaEventCreateWithFlags(&evIn,  cudaEventDisableTiming);
        cudaEventCreateWithFlags(&evWe1, cudaEventDisableTiming);
        cudaEventCreateWithFlags(&evWe2, cudaEventDisableTiming);
        cudaEventCreateWithFlags(&evWv,  cudaEventDisableTiming);
        cudaEventCreateWithFlags(&evWt1, cudaEventDisableTiming);
        cudaEventCreateWithFlags(&evWl,  cudaEventDisableTiming);
        cudaEventCreateWithFlags(&evWn,  cudaEventDisableTiming);
    }

    dim3 tb(16, 16);

    // fork: side stream handles all weight conversions + q/wn prep
    cudaEventRecord(evIn, 0);
    cudaStreamWaitEvent(sW, evIn, 0);

    transpose_f16_k<<<dim3(DH / 32, DH / 32, NEXP), tb, 0, sW>>>(We1, We1t, DH, DH, DH, (size_t)DH * DH);
    cudaEventRecord(evWe1, sW);
    transpose_f16_k<<<dim3(DH / 32, DH / 32, NEXP), tb, 0, sW>>>(We2, We2t, DH, DH, DH, (size_t)DH * DH);
    cudaEventRecord(evWe2, sW);
    prep_k<<<1, 256, 0, sW>>>(Wq, bq, bk, task);
    wn_k<<<NEXP * DH / 8, 256, 0, sW>>>(Wk);
    cudaEventRecord(evWn, sW);
    transpose_f16_k<<<dim3(DH / 32, DVV / 32, NEXP), tb, 0, sW>>>(Wv, Wvt, DH, DVV, NDH8, (size_t)DH);
    cudaEventRecord(evWv, sW);
    transpose_split_k<<<dim3(DVV / 32, DH / 32, 1), tb, 0, sW>>>(Wt1, Wt1h, Wt1l, DVV, DH, DVV, 0);
    cudaEventRecord(evWt1, sW);
    transpose_split_k<<<dim3(DH / 32, NOUT / 32, 1), tb, 0, sW>>>(Wl, Wlh, Wll, DH, NOUT, DH, 0);
    cudaEventRecord(evWl, sW);

    // main chain
    split_k<<<(BATCH * OBSD / 4 + 255) / 256, 256>>>(x, xh, xl, BATCH * OBSD);
    ts_base_k<<<dim3(32, 32, 2), tb>>>(Wb1, Wb1h, Wb1l, Wb2, Wb2h, Wb2l);

    mma_gemm3<EPI_RELU_R><<<dim3(8, 32), 128, SMEM_P3>>>(
        xh, xl, OBSD, Wb1h, Wb1l, OBSD, bb1, OBSD, nullptr, h1h, h1l, DH);
    mma_gemm3<EPI_RELU_S><<<dim3(8, 32), 128, SMEM_P3>>>(
        h1h, h1l, DH, Wb2h, Wb2l, DH, bb2, DH, nullptr, hh, nullptr, DH);

    cudaStreamWaitEvent(0, evWe1, 0);
    mma_gemm1<EPI_RELU_S><<<dim3(NDH8 / 128, 32), 128, SMEM1>>>(
        hh, DH, 0, We1t, DH, 0, be1, 0, DH, e1h, nullptr, NDH8, 0, nullptr, nullptr);

    cudaStreamWaitEvent(0, evWe2, 0);
    mma_gemm1<EPI_RELU_S><<<dim3(DH / 128, 32, NEXP), 128, SMEM1>>>(
        e1h, NDH8, DH, We2t, DH, DH * DH, be2, DH, DH, e2h, nullptr, NDH8, DH,
        nullptr, nullptr);

    cudaStreamWaitEvent(0, evWn, 0);
    expkq_scale_k<<<dim3(BATCH / 8, NEXP), 256>>>();

    cudaStreamWaitEvent(0, evWv, 0);
    mma_gemm1<EPI_VSUM><<<dim3(DVV / 128, 32), 128, SMEM1>>>(
        vth, NDH8, 0, Wvt, NDH8, 0, nullptr, 0, NDH8, rh, rl, DVV, 0, sc, bv);

    cudaStreamWaitEvent(0, evWt1, 0);
    mma_gemm3<EPI_RELU_R><<<dim3(DH / 128, 32), 128, SMEM_P3>>>(
        rh, rl, DVV, Wt1h, Wt1l, DVV, bt1, DVV, nullptr, th, tl, DH);

    cudaStreamWaitEvent(0, evWl, 0);
    mma_gemm3<EPI_SPLIT><<<dim3(1, 32), 128, SMEM_P3>>>(
        th, tl, DH, Wlh, Wll, DH, bl, DH, out, nullptr, nullptr, NOUT);
}